// round 1
// baseline (speedup 1.0000x reference)
#include <cuda_runtime.h>

#define BATCH   16
#define NPTS    4096
#define TILE    1024
#define THREADS 256
#define PPT     4   // x-points per thread -> block covers 1024 points

__device__ double g_acc[2];

__global__ void zero_acc_kernel() {
    if (threadIdx.x < 2) g_acc[threadIdx.x] = 0.0;
}

__global__ __launch_bounds__(THREADS) void chamfer_kernel(
    const float* __restrict__ xyz1, const float* __restrict__ xyz2)
{
    const int dir = blockIdx.z;                  // 0: x=xyz1 vs y=xyz2, 1: swapped
    const float* __restrict__ xs = (dir == 0) ? xyz1 : xyz2;
    const float* __restrict__ ys = (dir == 0) ? xyz2 : xyz1;
    const int b    = blockIdx.y;
    const int base = blockIdx.x * (THREADS * PPT);
    const int tid  = threadIdx.x;

    __shared__ float4 tile[TILE];

    // Load this thread's x-points into registers.
    float x0[PPT], x1[PPT], x2[PPT], mn[PPT], sq1[PPT];
#pragma unroll
    for (int p = 0; p < PPT; p++) {
        int n = base + tid + p * THREADS;
        const float* xp = xs + ((size_t)b * NPTS + n) * 3;
        x0[p] = xp[0]; x1[p] = xp[1]; x2[p] = xp[2];
        sq1[p] = x0[p] * x0[p] + x1[p] * x1[p] + x2[p] * x2[p];
        mn[p]  = 3.4e38f;
    }

    for (int t0 = 0; t0 < NPTS; t0 += TILE) {
        __syncthreads();
        // Stage candidate tile as (-2*y, ||y||^2)
#pragma unroll
        for (int j = 0; j < TILE / THREADS; j++) {
            int ml = tid + j * THREADS;
            int m  = t0 + ml;
            const float* yp = ys + ((size_t)b * NPTS + m) * 3;
            float a = yp[0], c = yp[1], d = yp[2];
            tile[ml] = make_float4(-2.0f * a, -2.0f * c, -2.0f * d,
                                   a * a + c * c + d * d);
        }
        __syncthreads();

#pragma unroll 4
        for (int i = 0; i < TILE; i++) {
            float4 cv = tile[i];   // warp-broadcast, conflict-free
#pragma unroll
            for (int p = 0; p < PPT; p++) {
                float t = fmaf(x0[p], cv.x,
                          fmaf(x1[p], cv.y,
                          fmaf(x2[p], cv.z, cv.w)));
                mn[p] = fminf(mn[p], t);
            }
        }
    }

    // Per-thread sum of final distances (add back sq1 now).
    float s = 0.0f;
#pragma unroll
    for (int p = 0; p < PPT; p++) s += mn[p] + sq1[p];

    // Block reduction: warp shuffle + smem + one atomic per block.
    __shared__ float red[THREADS / 32];
#pragma unroll
    for (int o = 16; o > 0; o >>= 1) s += __shfl_down_sync(0xffffffffu, s, o);
    if ((tid & 31) == 0) red[tid >> 5] = s;
    __syncthreads();
    if (tid < THREADS / 32) {
        s = red[tid];
#pragma unroll
        for (int o = (THREADS / 64); o > 0; o >>= 1)
            s += __shfl_down_sync(0xffu, s, o);
        if (tid == 0) atomicAdd(&g_acc[dir], (double)s);
    }
}

__global__ void finalize_kernel(float* out) {
    if (threadIdx.x < 2)
        out[threadIdx.x] = (float)(g_acc[threadIdx.x] / (double)(BATCH * NPTS));
}

extern "C" void kernel_launch(void* const* d_in, const int* in_sizes, int n_in,
                              void* d_out, int out_size)
{
    const float* xyz1 = (const float*)d_in[0];
    const float* xyz2 = (const float*)d_in[1];
    float* out = (float*)d_out;

    zero_acc_kernel<<<1, 32>>>();
    dim3 grid(NPTS / (THREADS * PPT), BATCH, 2);   // (4, 16, 2) = 128 blocks
    chamfer_kernel<<<grid, THREADS>>>(xyz1, xyz2);
    finalize_kernel<<<1, 32>>>(out);
}